// round 8
// baseline (speedup 1.0000x reference)
#include <cuda_runtime.h>
#include <cuda_bf16.h>
#include <stdint.h>
#include <math.h>

#define S   2048
#define DIN 256
#define DM  512
#define NB  4
#define H   8
#define DK  64
#define BH  32
#define PAD 72

__device__ __nv_bfloat16 g_Qc[(size_t)BH * S * 128];   // [n][s][hi(64)|lo(64)]
__device__ __nv_bfloat16 g_Kc[(size_t)BH * S * 128];
__device__ __nv_bfloat16 g_Vhi[(size_t)BH * DK * S];   // [n][c][s]
__device__ __nv_bfloat16 g_Vlo[(size_t)BH * DK * S];
__device__ float g_inv[(size_t)BH * S];
__device__ float g_AO[(size_t)NB * S * DM];
__device__ float g_scratch[(size_t)NB * H * S * S];

__device__ __forceinline__ uint32_t smem_u32(const void* p) {
    uint32_t a;
    asm("{ .reg .u64 t; cvta.to.shared.u64 t, %1; cvt.u32.u64 %0, t; }" : "=r"(a) : "l"(p));
    return a;
}
__device__ __forceinline__ void ldsm4(uint32_t addr, uint32_t& r0, uint32_t& r1,
                                      uint32_t& r2, uint32_t& r3) {
    asm volatile("ldmatrix.sync.aligned.m8n8.x4.shared.b16 {%0,%1,%2,%3}, [%4];"
                 : "=r"(r0), "=r"(r1), "=r"(r2), "=r"(r3) : "r"(addr));
}
__device__ __forceinline__ void mma16816(float* c, const uint32_t* a, uint32_t b0, uint32_t b1) {
    asm volatile(
        "mma.sync.aligned.m16n8k16.row.col.f32.bf16.bf16.f32 "
        "{%0,%1,%2,%3},{%4,%5,%6,%7},{%8,%9},{%0,%1,%2,%3};"
        : "+f"(c[0]), "+f"(c[1]), "+f"(c[2]), "+f"(c[3])
        : "r"(a[0]), "r"(a[1]), "r"(a[2]), "r"(a[3]), "r"(b0), "r"(b1));
}
__device__ __forceinline__ void cp16(uint32_t s, const void* g) {
    asm volatile("cp.async.cg.shared.global [%0], [%1], 16;" :: "r"(s), "l"(g));
}
#define CP_COMMIT() asm volatile("cp.async.commit_group;" ::: "memory")
#define CP_WAIT0()  asm volatile("cp.async.wait_group 0;" ::: "memory")

// ---------------------------------------------------------------------------
// K1: QKV projection (fp32 SIMT) + bf16 hi/lo emission
// ---------------------------------------------------------------------------
__global__ __launch_bounds__(256) void qkv_kernel(
    const float* __restrict__ x,
    const float* __restrict__ Wq, const float* __restrict__ bq,
    const float* __restrict__ Wk, const float* __restrict__ bk,
    const float* __restrict__ Wv, const float* __restrict__ bv)
{
    const int s0 = blockIdx.x * 64, m0 = blockIdx.y * 64, b = blockIdx.z;
    __shared__ float sX[16][64];
    __shared__ float sW[3][64][16];
    const int tid = threadIdx.x, tx = tid & 15, ty = tid >> 4;
    float acc[3][4][4];
#pragma unroll
    for (int w = 0; w < 3; w++)
#pragma unroll
        for (int i = 0; i < 4; i++)
#pragma unroll
            for (int j = 0; j < 4; j++) acc[w][i][j] = 0.f;

    for (int d0 = 0; d0 < DIN; d0 += 16) {
        {
            int dd = tid >> 4, sv = (tid & 15) * 4;
            *(float4*)&sX[dd][sv] = *(const float4*)(x + (size_t)(b * DIN + d0 + dd) * S + s0 + sv);
        }
        {
            int mm = tid >> 2, dv = (tid & 3) * 4;
            const int wofs = (m0 + mm) * DIN + d0 + dv;
            *(float4*)&sW[0][mm][dv] = *(const float4*)(Wq + wofs);
            *(float4*)&sW[1][mm][dv] = *(const float4*)(Wk + wofs);
            *(float4*)&sW[2][mm][dv] = *(const float4*)(Wv + wofs);
        }
        __syncthreads();
#pragma unroll
        for (int dd = 0; dd < 16; dd++) {
            float xb[4];
            *(float4*)xb = *(float4*)&sX[dd][tx * 4];
#pragma unroll
            for (int w = 0; w < 3; w++) {
                float wr[4];
#pragma unroll
                for (int i = 0; i < 4; i++) wr[i] = sW[w][ty * 4 + i][dd];
#pragma unroll
                for (int i = 0; i < 4; i++)
#pragma unroll
                    for (int j = 0; j < 4; j++) acc[w][i][j] += wr[i] * xb[j];
            }
        }
        __syncthreads();
    }

    const int n = b * 8 + (m0 >> 6);
    const float* bs[3] = {bq, bk, bv};
#pragma unroll
    for (int w = 0; w < 3; w++) {
        float v[4][4];
#pragma unroll
        for (int i = 0; i < 4; i++) {
            float bb = bs[w][m0 + ty * 4 + i];
#pragma unroll
            for (int j = 0; j < 4; j++) v[i][j] = acc[w][i][j] + bb;
        }
        if (w < 2) {
            __nv_bfloat16* dst = (w == 0) ? g_Qc : g_Kc;
#pragma unroll
            for (int j = 0; j < 4; j++) {
                __align__(8) __nv_bfloat16 hi[4], lo[4];
#pragma unroll
                for (int i = 0; i < 4; i++) {
                    float p = v[i][j];
                    hi[i] = __float2bfloat16(p);
                    lo[i] = __float2bfloat16(p - __bfloat162float(hi[i]));
                }
                size_t off = ((size_t)n * S + s0 + tx * 4 + j) * 128 + ty * 4;
                *(uint2*)(dst + off) = *(uint2*)hi;
                *(uint2*)(dst + off + 64) = *(uint2*)lo;
            }
        } else {
#pragma unroll
            for (int i = 0; i < 4; i++) {
                __align__(8) __nv_bfloat16 hi[4], lo[4];
#pragma unroll
                for (int j = 0; j < 4; j++) {
                    float p = v[i][j];
                    hi[j] = __float2bfloat16(p);
                    lo[j] = __float2bfloat16(p - __bfloat162float(hi[j]));
                }
                size_t off = ((size_t)n * DK + ty * 4 + i) * S + s0 + tx * 4;
                *(uint2*)(g_Vhi + off) = *(uint2*)hi;
                *(uint2*)(g_Vlo + off) = *(uint2*)lo;
            }
        }
    }
}

// ---------------------------------------------------------------------------
// K2 (fused): per (n, q-tile 128): loop 32 k-chunks of 64:
//   QK MMA -> exp -> rowsum (regs) -> P hi/lo SMEM -> AV MMA accumulate.
// End: inv = 1/rowsum, write g_inv, scale O, scatter. E never hits DRAM.
// ---------------------------------------------------------------------------
__global__ __launch_bounds__(256) void fused_kernel()
{
    extern __shared__ char smp[];
    __nv_bfloat16* sQh = (__nv_bfloat16*)smp;          // [128][PAD]
    __nv_bfloat16* sQl = sQh + 128 * PAD;
    __nv_bfloat16* sKh = sQl + 128 * PAD;              // [64][PAD]
    __nv_bfloat16* sKl = sKh + 64 * PAD;
    __nv_bfloat16* sVh = sKl + 64 * PAD;               // [64][PAD]
    __nv_bfloat16* sVl = sVh + 64 * PAD;
    __nv_bfloat16* sPh = sVl + 64 * PAD;               // [128][PAD]
    __nv_bfloat16* sPl = sPh + 128 * PAD;
    __shared__ float sRS[128][2];
    const int qb = blockIdx.x * 128, n = blockIdx.y;
    const int tid = threadIdx.x, wid = tid >> 5, lane = tid & 31;
    const int wm = wid >> 1, wn = wid & 1;
    const int g = lane >> 2, c = lane & 3;

    const __nv_bfloat16* Qg = g_Qc + ((size_t)n * S + qb) * 128;
    const __nv_bfloat16* Kg = g_Kc + (size_t)n * S * 128;
    const __nv_bfloat16* Vh = g_Vhi + (size_t)n * DK * S;
    const __nv_bfloat16* Vl = g_Vlo + (size_t)n * DK * S;

    // Q tiles: persistent
    for (int u = tid; u < 2048; u += 256) {
        int row = u >> 4, ch = u & 15;
        cp16(smem_u32((ch < 8 ? sQh : sQl) + row * PAD + (ch & 7) * 8),
             Qg + row * 128 + ch * 8);
    }
    CP_COMMIT();

    float accO[8][4];
#pragma unroll
    for (int f = 0; f < 8; f++)
#pragma unroll
        for (int e = 0; e < 4; e++) accO[f][e] = 0.f;
    float rs[4] = {0.f, 0.f, 0.f, 0.f};

    const uint32_t uQh = smem_u32(sQh), uQl = smem_u32(sQl);
    const uint32_t uKh = smem_u32(sKh), uKl = smem_u32(sKl);
    const uint32_t uVh = smem_u32(sVh), uVl = smem_u32(sVl);
    const uint32_t uPh = smem_u32(sPh), uPl = smem_u32(sPl);
    const int arow = wm * 32 + (lane & 15);
    const int acol8 = (lane >> 4) << 3;
    const int brow = wn * 32 + (lane & 7) + ((lane >> 4) << 3);
    const int bcol8 = ((lane >> 3) & 1) << 3;

    CP_WAIT0();
    __syncthreads();

    for (int kt = 0; kt < 32; kt++) {
        const int kb = kt * 64;
        // load K chunk [64 rows][hi|lo 64c] and V chunk [64 c][64 k] hi/lo
        for (int u = tid; u < 1024; u += 256) {
            int r = u >> 4, ch = u & 15;
            cp16(smem_u32((ch < 8 ? sKh : sKl) + r * PAD + (ch & 7) * 8),
                 Kg + (size_t)(kb + r) * 128 + ch * 8);
        }
        for (int u = tid; u < 1024; u += 256) {
            int tier = u >> 9, cc = (u >> 3) & 63, ch = u & 7;
            cp16(smem_u32((tier ? sVl : sVh) + cc * PAD + ch * 8),
                 (tier ? Vl : Vh) + (size_t)cc * S + kb + ch * 8);
        }
        CP_COMMIT();
        CP_WAIT0();
        __syncthreads();

        // ---- QK: M=128q, N=64k, contraction c=64 ----
        float acc2[8][4];
#pragma unroll
        for (int f = 0; f < 8; f++)
#pragma unroll
            for (int e = 0; e < 4; e++) acc2[f][e] = 0.f;
#pragma unroll
        for (int ks = 0; ks < 4; ks++) {
            const int k0 = ks * 16;
            uint32_t ah[2][4], al[2][4];
#pragma unroll
            for (int mf = 0; mf < 2; mf++) {
                uint32_t off = (uint32_t)((arow + mf * 16) * PAD + k0 + acol8) * 2;
                ldsm4(uQh + off, ah[mf][0], ah[mf][1], ah[mf][2], ah[mf][3]);
                ldsm4(uQl + off, al[mf][0], al[mf][1], al[mf][2], al[mf][3]);
            }
#pragma unroll
            for (int nf2 = 0; nf2 < 2; nf2++) {
                uint32_t boff = (uint32_t)((brow + nf2 * 16) * PAD + k0 + bcol8) * 2;
                uint32_t bh[4], bl[4];
                ldsm4(uKh + boff, bh[0], bh[1], bh[2], bh[3]);
                ldsm4(uKl + boff, bl[0], bl[1], bl[2], bl[3]);
#pragma unroll
                for (int mf = 0; mf < 2; mf++) {
                    float* c0 = acc2[mf * 4 + nf2 * 2];
                    float* c1 = acc2[mf * 4 + nf2 * 2 + 1];
                    mma16816(c0, ah[mf], bh[0], bh[1]);
                    mma16816(c0, al[mf], bh[0], bh[1]);
                    mma16816(c0, ah[mf], bl[0], bl[1]);
                    mma16816(c1, ah[mf], bh[2], bh[3]);
                    mma16816(c1, al[mf], bh[2], bh[3]);
                    mma16816(c1, ah[mf], bl[2], bl[3]);
                }
            }
        }

        // ---- exp + rowsum + P hi/lo into SMEM ----
#pragma unroll
        for (int mf = 0; mf < 2; mf++)
#pragma unroll
            for (int nf = 0; nf < 4; nf++) {
                float* a = acc2[mf * 4 + nf];
                int r0 = wm * 32 + mf * 16 + g, col = wn * 32 + nf * 8 + c * 2;
                float e0 = __expf(a[0]), e1 = __expf(a[1]);
                float e2 = __expf(a[2]), e3 = __expf(a[3]);
                rs[mf * 2] += e0 + e1;
                rs[mf * 2 + 1] += e2 + e3;
                __align__(4) __nv_bfloat16 hb[2], lb[2];
                hb[0] = __float2bfloat16(e0);
                hb[1] = __float2bfloat16(e1);
                lb[0] = __float2bfloat16(e0 - __bfloat162float(hb[0]));
                lb[1] = __float2bfloat16(e1 - __bfloat162float(hb[1]));
                *(uint32_t*)(sPh + r0 * PAD + col) = *(uint32_t*)hb;
                *(uint32_t*)(sPl + r0 * PAD + col) = *(uint32_t*)lb;
                hb[0] = __float2bfloat16(e2);
                hb[1] = __float2bfloat16(e3);
                lb[0] = __float2bfloat16(e2 - __bfloat162float(hb[0]));
                lb[1] = __float2bfloat16(e3 - __bfloat162float(hb[1]));
                *(uint32_t*)(sPh + (r0 + 8) * PAD + col) = *(uint32_t*)hb;
                *(uint32_t*)(sPl + (r0 + 8) * PAD + col) = *(uint32_t*)lb;
            }
        __syncthreads();

        // ---- AV: M=128q, N=64c, contraction k=64 ----
#pragma unroll
        for (int ks = 0; ks < 4; ks++) {
            const int k0 = ks * 16;
            uint32_t ah[2][4], al[2][4];
#pragma unroll
            for (int mf = 0; mf < 2; mf++) {
                uint32_t off = (uint32_t)((arow + mf * 16) * PAD + k0 + acol8) * 2;
                ldsm4(uPh + off, ah[mf][0], ah[mf][1], ah[mf][2], ah[mf][3]);
                ldsm4(uPl + off, al[mf][0], al[mf][1], al[mf][2], al[mf][3]);
            }
#pragma unroll
            for (int nf2 = 0; nf2 < 2; nf2++) {
                uint32_t boff = (uint32_t)((brow + nf2 * 16) * PAD + k0 + bcol8) * 2;
                uint32_t bh[4], bl[4];
                ldsm4(uVh + boff, bh[0], bh[1], bh[2], bh[3]);
                ldsm4(uVl + boff, bl[0], bl[1], bl[2], bl[3]);
#pragma unroll
                for (int mf = 0; mf < 2; mf++) {
                    float* c0 = accO[mf * 4 + nf2 * 2];
                    float* c1 = accO[mf * 4 + nf2 * 2 + 1];
                    mma16816(c0, ah[mf], bh[0], bh[1]);
                    mma16816(c0, al[mf], bh[0], bh[1]);
                    mma16816(c0, ah[mf], bl[0], bl[1]);
                    mma16816(c1, ah[mf], bh[2], bh[3]);
                    mma16816(c1, al[mf], bh[2], bh[3]);
                    mma16816(c1, ah[mf], bl[2], bl[3]);
                }
            }
        }
        __syncthreads();
    }

    // ---- rowsums: reduce over c lanes, combine wn halves via SMEM ----
#pragma unroll
    for (int off = 1; off <= 2; off <<= 1)
#pragma unroll
        for (int i = 0; i < 4; i++) rs[i] += __shfl_xor_sync(0xffffffffu, rs[i], off);
    if (c == 0) {
#pragma unroll
        for (int mf = 0; mf < 2; mf++)
#pragma unroll
            for (int hh = 0; hh < 2; hh++)
                sRS[wm * 32 + mf * 16 + g + hh * 8][wn] = rs[mf * 2 + hh];
    }
    __syncthreads();
    if (wn == 0 && c == 0) {
#pragma unroll
        for (int mf = 0; mf < 2; mf++)
#pragma unroll
            for (int hh = 0; hh < 2; hh++) {
                int row = wm * 32 + mf * 16 + g + hh * 8;
                g_inv[(size_t)n * S + qb + row] = 1.f / (sRS[row][0] + sRS[row][1]);
            }
    }

    // ---- scale O by inv, scatter into torch-faithful [B,S,DM] ----
#pragma unroll
    for (int mf = 0; mf < 2; mf++)
#pragma unroll
        for (int nf = 0; nf < 4; nf++) {
            float* a = accO[mf * 4 + nf];
            int col = wn * 32 + nf * 8 + c * 2;
#pragma unroll
            for (int hh = 0; hh < 2; hh++) {
                int row = wm * 32 + mf * 16 + g + hh * 8;
                float inv = 1.f / (sRS[row][0] + sRS[row][1]);
                int q = qb + row;
                float* dst = g_AO + ((size_t)(q >> 9) * S + ((q & 511) << 2) + (n >> 3)) * DM +
                             (n & 7) * 64 + col;
                float2 v;
                v.x = a[hh * 2] * inv;
                v.y = a[hh * 2 + 1] * inv;
                *(float2*)dst = v;
            }
        }
}

// ---------------------------------------------------------------------------
// K3: attn_w writer — recompute QK per 128x128 tile, attn = exp(s) * inv.
// ---------------------------------------------------------------------------
__global__ __launch_bounds__(256) void attn_kernel(float* __restrict__ attn)
{
    extern __shared__ char smp[];
    __nv_bfloat16* sQh = (__nv_bfloat16*)smp;       // [128][PAD]
    __nv_bfloat16* sQl = sQh + 128 * PAD;
    __nv_bfloat16* sKh = sQl + 128 * PAD;
    __nv_bfloat16* sKl = sKh + 128 * PAD;
    __shared__ float sInv[128];
    const int kb = blockIdx.x * 128, qb = blockIdx.y * 128, n = blockIdx.z;
    const int tid = threadIdx.x, wid = tid >> 5, lane = tid & 31;
    const int wm = wid >> 1, wn = wid & 1;

    const __nv_bfloat16* Qg = g_Qc + ((size_t)n * S + qb) * 128;
    const __nv_bfloat16* Kg = g_Kc + ((size_t)n * S + kb) * 128;
    for (int u = tid; u < 2048; u += 256) {
        int row = u >> 4, ch = u & 15;
        cp16(smem_u32((ch < 8 ? sQh : sQl) + row * PAD + (ch & 7) * 8), Qg + row * 128 + ch * 8);
        cp16(smem_u32((ch < 8 ? sKh : sKl) + row * PAD + (ch & 7) * 8), Kg + row * 128 + ch * 8);
    }
    CP_COMMIT();
    if (tid < 128) sInv[tid] = g_inv[(size_t)n * S + qb + tid];
    CP_WAIT0();
    __syncthreads();

    float acc[16][4];
#pragma unroll
    for (int f = 0; f < 16; f++)
#pragma unroll
        for (int e = 0; e < 4; e++) acc[f][e] = 0.f;

    const uint32_t uQh = smem_u32(sQh), uQl = smem_u32(sQl);
    const uint32_t uKh = smem_u32(sKh), uKl = smem_u32(sKl);
    const int arow = wm * 32 + (lane & 15);
    const int acol8 = (lane >> 4) << 3;
    const int brow = wn * 64 + (lane & 7) + ((lane >> 4) << 3);
    const int bcol8 = ((lane >> 3) & 1) << 3;

#pragma unroll
    for (int ks = 0; ks < 4; ks++) {
        const int k0 = ks * 16;
        uint32_t ah[2][4], al[2][4];
#pragma unroll
        for (int mf = 0; mf < 2; mf++) {
            uint32_t off = (uint32_t)((arow + mf * 16) * PAD + k0 + acol8) * 2;
            ldsm4(uQh + off, ah[mf][0], ah[mf][1], ah[mf][2], ah[mf][3]);
            ldsm4(uQl + off, al[mf][0], al[mf][1], al[mf][2], al[mf][3]);
        }
#pragma unroll
        for (int nf2 = 0; nf2 < 4; nf2++) {
            uint32_t boff = (uint32_t)((brow + nf2 * 16) * PAD + k0 + bcol8) * 2;
            uint32_t bh[4], bl[4];
            ldsm4(uKh + boff, bh[0], bh[1], bh[2], bh[3]);
            ldsm4(uKl + boff, bl[0], bl[1], bl[2], bl[3]);
#pragma unroll
            for (int mf = 0; mf < 2; mf++) {
                float* c0 = acc[mf * 8 + nf2 * 2];
                float* c1 = acc[mf * 8 + nf2 * 2 + 1];
                mma16816(c0, ah[mf], bh[0], bh[1]);
                mma16816(c0, al[mf], bh[0], bh[1]);
                mma16816(c0, ah[mf], bl[0], bl[1]);
                mma16816(c1, ah[mf], bh[2], bh[3]);
                mma16816(c1, al[mf], bh[2], bh[3]);
                mma16816(c1, ah[mf], bl[2], bl[3]);
            }
        }
    }
    __syncthreads();

    float* sS = (float*)smp;  // [128][132] staging (aliases tiles)
    const int g = lane >> 2, c = lane & 3;
#pragma unroll
    for (int mf = 0; mf < 2; mf++)
#pragma unroll
        for (int nf = 0; nf < 8; nf++) {
            float* a = acc[mf * 8 + nf];
            int r0 = wm * 32 + mf * 16 + g, col = wn * 64 + nf * 8 + c * 2;
            float i0 = sInv[r0], i1 = sInv[r0 + 8];
            sS[r0 * 132 + col] = __expf(a[0]) * i0;
            sS[r0 * 132 + col + 1] = __expf(a[1]) * i0;
            sS[(r0 + 8) * 132 + col] = __expf(a[2]) * i1;
            sS[(r0 + 8) * 132 + col + 1] = __expf(a[3]) * i1;
        }
    __syncthreads();
    for (int it = tid; it < 4096; it += 256) {
        int row = it >> 5, c4 = it & 31;
        __stcs((float4*)(attn + ((size_t)n * S + qb + row) * S + kb + c4 * 4),
               *(float4*)(sS + row * 132 + c4 * 4));
    }
}

// ---------------------------------------------------------------------------
// K4: out-projection
// ---------------------------------------------------------------------------
__global__ __launch_bounds__(256) void proj_kernel(
    const float* __restrict__ Wo, const float* __restrict__ bo, float* __restrict__ Z)
{
    const int s0 = blockIdx.x * 64, d0 = blockIdx.y * 64, bp = blockIdx.z;
    __shared__ float sW[64][33];
    __shared__ float sA[64][33];
    const int tid = threadIdx.x, tx = tid & 15, ty = tid >> 4;
    float acc[4][4] = {};
    for (int m0 = 0; m0 < DM; m0 += 32) {
#pragma unroll
        for (int r = 0; r < 2; r++) {
            int row = (tid >> 3) + r * 32, cv = (tid & 7) * 4;
            float4 w4 = *(const float4*)(Wo + (size_t)(d0 + row) * DM + m0 + cv);
            float4 a4 = *(const float4*)(g_AO + ((size_t)bp * S + s0 + row) * DM + m0 + cv);
            sW[row][cv] = w4.x; sW[row][cv + 1] = w4.y; sW[row][cv + 2] = w4.z; sW[row][cv + 3] = w4.w;
            sA[row][cv] = a4.x; sA[row][cv + 1] = a4.y; sA[row][cv + 2] = a4.z; sA[row][cv + 3] = a4.w;
        }
        __syncthreads();
#pragma unroll
        for (int kk = 0; kk < 32; kk++) {
            float a[4], c4[4];
#pragma unroll
            for (int i = 0; i < 4; i++) { a[i] = sW[ty * 4 + i][kk]; c4[i] = sA[tx * 4 + i][kk]; }
#pragma unroll
            for (int i = 0; i < 4; i++)
#pragma unroll
                for (int j = 0; j < 4; j++) acc[i][j] += a[i] * c4[j];
        }
        __syncthreads();
    }
#pragma unroll
    for (int i = 0; i < 4; i++) {
        int d = d0 + ty * 4 + i;
        float bias = bo[d];
        float4 r;
        r.x = acc[i][0] + bias; r.y = acc[i][1] + bias;
        r.z = acc[i][2] + bias; r.w = acc[i][3] + bias;
        *(float4*)(Z + (size_t)(bp * DIN + d) * S + s0 + tx * 4) = r;
    }
}

// ---------------------------------------------------------------------------
extern "C" void kernel_launch(void* const* d_in, const int* in_sizes, int n_in,
                              void* d_out, int out_size)
{
    const float* x  = (const float*)d_in[0];
    const float* Wq = (const float*)d_in[1];
    const float* bq = (const float*)d_in[2];
    const float* Wk = (const float*)d_in[3];
    const float* bk = (const float*)d_in[4];
    const float* Wv = (const float*)d_in[5];
    const float* bv = (const float*)d_in[6];
    const float* Wo = (const float*)d_in[7];
    const float* bo = (const float*)d_in[8];
    float* out = (float*)d_out;

    const long long zsz = (long long)NB * DIN * S;
    const long long asz = (long long)NB * H * S * S;
    float* attn;
    if ((long long)out_size >= zsz + asz) {
        attn = out + zsz;
    } else {
        void* p = nullptr;
        cudaGetSymbolAddress(&p, g_scratch);
        attn = (float*)p;
    }

    const int fused_smem = (2 * 128 + 4 * 64 + 2 * 128) * PAD * 2;  // 110,592 B
    const int attn_smem  = 4 * 128 * PAD * 2;                        // 73,728 B
    cudaFuncSetAttribute(fused_kernel, cudaFuncAttributeMaxDynamicSharedMemorySize, fused_smem);
    cudaFuncSetAttribute(attn_kernel, cudaFuncAttributeMaxDynamicSharedMemorySize, attn_smem);

    qkv_kernel<<<dim3(S / 64, DM / 64, NB), 256>>>(x, Wq, bq, Wk, bk, Wv, bv);
    fused_kernel<<<dim3(16, BH), 256, fused_smem>>>();
    attn_kernel<<<dim3(16, 16, BH), 256, attn_smem>>>(attn);
    proj_kernel<<<dim3(S / 64, DIN / 64, NB), 256>>>(Wo, bo, out);
}